// round 10
// baseline (speedup 1.0000x reference)
#include <cuda_runtime.h>

// B=2, S=2048, D=1024, H=16, HS=64
// out = V @ (K^T @ V) / 8 per (b,h)   (no softmax, Q==V)
// mma.sync m16n8k8 tf32 + cp.async, K-permuted operands (LDS.64 frags).
// R10: software-pipelined fragment double-buffering — load ks+1 fragments
// while issuing ks MMAs. Removes 3/4 of the exposed LDS->HMMA chains per kc.

#define S_LEN 2048
#define D_DIM 1024
#define HS    64
#define BH    32
#define MROWS 4096

// k-group permutation: store order [k0,k4,k1,k5,k2,k6,k3,k7] so fragment
// pairs (tg, tg+4) are adjacent -> LDS.64. Same perm on A and B => exact.
#define PERMK(i) (((i) & ~7) | ((((i) & 7) < 4) ? (((i) & 7) << 1) \
                                                : ((((i) & 7) - 4) * 2 + 1)))

// ---------------- scratch (no allocs allowed) ----------------
__device__ float g_K[BH * S_LEN * HS];        // [B,H,S,HS] fp32, natural
__device__ float g_V[BH * S_LEN * HS];        // [B,H,S,HS] fp32, natural
__device__ float g_Mpart[BH * 8 * HS * HS];
__device__ float g_M[BH * HS * HS];
__device__ float g_A[MROWS * D_DIM];          // tf32, k-PERMUTED columns
__device__ float g_Xtf[MROWS * D_DIM];        // x tf32, k-PERMUTED columns
__device__ float g_Wt[2048 * 1024];           // [Wk|Wv] K-major, k-PERMUTED
__device__ float g_Wpt[1024 * 1024];          // Wproj^T K-major, k-PERMUTED

// =============================================================
// helpers
// =============================================================
__device__ __forceinline__ float f2tf32(float f) {
    unsigned u;
    asm("cvt.rna.tf32.f32 %0, %1;" : "=r"(u) : "f"(f));
    return __uint_as_float(u);
}

__device__ __forceinline__ void cp16(void* dst, const void* src) {
    unsigned d;
    asm("{ .reg .u64 t; cvta.to.shared.u64 t, %1; cvt.u32.u64 %0, t; }"
        : "=r"(d) : "l"(dst));
    asm volatile("cp.async.cg.shared.global [%0], [%1], 16;" :: "r"(d), "l"(src));
}

__device__ __forceinline__ void mma8(float* d, const float* a, const float* b) {
    asm volatile(
        "mma.sync.aligned.m16n8k8.row.col.f32.tf32.tf32.f32 "
        "{%0,%1,%2,%3}, {%4,%5,%6,%7}, {%8,%9}, {%0,%1,%2,%3};"
        : "+f"(d[0]), "+f"(d[1]), "+f"(d[2]), "+f"(d[3])
        : "r"(__float_as_uint(a[0])), "r"(__float_as_uint(a[1])),
          "r"(__float_as_uint(a[2])), "r"(__float_as_uint(a[3])),
          "r"(__float_as_uint(b[0])), "r"(__float_as_uint(b[1])));
}

// =============================================================
// x -> tf32, k-permuted. One thread per 8-group.
// =============================================================
__global__ __launch_bounds__(256) void xcvt(const float* __restrict__ x)
{
    int base = (blockIdx.x * 256 + threadIdx.x) * 8;
    float4 v0 = *(const float4*)(x + base);
    float4 v1 = *(const float4*)(x + base + 4);
    *(float4*)(g_Xtf + base) = make_float4(f2tf32(v0.x), f2tf32(v1.x),
                                           f2tf32(v0.y), f2tf32(v1.y));
    *(float4*)(g_Xtf + base + 4) = make_float4(f2tf32(v0.z), f2tf32(v1.z),
                                               f2tf32(v0.w), f2tf32(v1.w));
}

// =============================================================
// Weight transposes -> K-major rows, tf32, k-permuted columns
// =============================================================
__global__ __launch_bounds__(256) void tW(const float* __restrict__ Wk,
                                          const float* __restrict__ Wv)
{
    __shared__ float tile[32][33];
    const int hh = blockIdx.z;
    const int x0 = blockIdx.x * 32;         // d tile (k-dim)
    const int y0 = blockIdx.y * 32;         // e tile
    const int tx = threadIdx.x, ty = threadIdx.y;
    const float* W = (hh < 16) ? Wk : Wv;
    const int h = hh & 15;
    #pragma unroll
    for (int j = 0; j < 4; j++)
        tile[ty + 8 * j][tx] = W[h * 65536 + (x0 + ty + 8 * j) * 64 + y0 + tx];
    __syncthreads();
    const int dp = x0 + PERMK(tx);
    #pragma unroll
    for (int j = 0; j < 4; j++)
        g_Wt[(hh * 64 + y0 + ty + 8 * j) * 1024 + dp] = f2tf32(tile[tx][ty + 8 * j]);
}

__global__ __launch_bounds__(256) void tWp(const float* __restrict__ Wp)
{
    __shared__ float tile[32][33];
    const int x0 = blockIdx.x * 32;   // n tile
    const int y0 = blockIdx.y * 32;   // k tile
    const int tx = threadIdx.x, ty = threadIdx.y;
    #pragma unroll
    for (int j = 0; j < 4; j++)
        tile[ty + 8 * j][tx] = Wp[(y0 + ty + 8 * j) * 1024 + x0 + tx];
    __syncthreads();
    const int kp = y0 + PERMK(tx);
    #pragma unroll
    for (int j = 0; j < 4; j++)
        g_Wpt[(x0 + ty + 8 * j) * 1024 + kp] = f2tf32(tile[tx][ty + 8 * j]);
}

// =============================================================
// tf32 mma.sync GEMM: C[4096, N] = A[4096,1024] @ B^T (k-permuted operands)
// BM=128, BN=256, BK=32, 3-stage / distance-2 prefetch, one sync per iter,
// fragment double-buffering across ks-groups.
// =============================================================
#define BMt 128
#define BNt 256
#define BKt 32
#define PITCH 40
#define SA_BYTES (BMt * PITCH * 4)             // 20480
#define SB_BYTES (BNt * PITCH * 4)             // 40960
#define STAGE_BYTES (SA_BYTES + SB_BYTES)      // 61440
#define GEMM_SMEM (3 * STAGE_BYTES)            // 184320

__global__ __launch_bounds__(256, 1)
void gemm_mma(const float* __restrict__ bias,
              float* __restrict__ Y,
              int mode)
{
    extern __shared__ __align__(16) char sm[];
    const int tid = threadIdx.x, wid = tid >> 5, lane = tid & 31;
    const int g = lane >> 2, tg = lane & 3;
    const int bm = blockIdx.y * BMt, bn = blockIdx.x * BNt;

    const float* Ag = ((mode == 0) ? g_Xtf : g_A) + (size_t)bm * 1024;
    const float* Bg = ((mode == 0) ? g_Wt : g_Wpt) + (size_t)bn * 1024;

    auto prefetch = [&](int kc) {
        char* sA = sm + (kc % 3) * STAGE_BYTES;
        char* sB = sA + SA_BYTES;
        const float* As = Ag + kc * BKt;
        const float* Bs = Bg + kc * BKt;
        #pragma unroll
        for (int i = 0; i < 4; i++) {
            int idx = tid + i * 256;
            int m = idx >> 3, k4 = idx & 7;
            cp16(sA + m * (PITCH * 4) + k4 * 16, As + (size_t)m * 1024 + k4 * 4);
        }
        #pragma unroll
        for (int i = 0; i < 8; i++) {
            int idx = tid + i * 256;
            int n = idx >> 3, k4 = idx & 7;
            cp16(sB + n * (PITCH * 4) + k4 * 16, Bs + (size_t)n * 1024 + k4 * 4);
        }
        asm volatile("cp.async.commit_group;" ::: "memory");
    };

    prefetch(0); prefetch(1);

    const int wm = (wid & 1) * 64;       // 2 warps along M
    const int wn = (wid >> 1) * 64;      // 4 warps along N

    float acc[4][8][4];
    #pragma unroll
    for (int mt = 0; mt < 4; mt++)
        #pragma unroll
        for (int nt = 0; nt < 8; nt++)
            #pragma unroll
            for (int q = 0; q < 4; q++) acc[mt][nt][q] = 0.f;

    float afr[2][4][4], bfr[2][8][2];

    for (int kc = 0; kc < 32; kc++) {
        const float* sA = (const float*)(sm + (kc % 3) * STAGE_BYTES);
        const float* sB = (const float*)((const char*)sA + SA_BYTES);
        if (kc < 31) asm volatile("cp.async.wait_group 1;" ::: "memory");
        else         asm volatile("cp.async.wait_group 0;" ::: "memory");
        __syncthreads();
        if (kc + 2 < 32) prefetch(kc + 2);

        // fragment loader for ks-group `ks` into slot `sl`
        auto ldfrag = [&](int ks, int sl) {
            const int kslot = ks * 8 + 2 * tg;
            #pragma unroll
            for (int mt = 0; mt < 4; mt++) {
                const float* p = sA + (wm + mt * 16 + g) * PITCH + kslot;
                float2 lo = *(const float2*)p;
                float2 hi = *(const float2*)(p + 8 * PITCH);
                afr[sl][mt][0] = lo.x; afr[sl][mt][1] = hi.x;
                afr[sl][mt][2] = lo.y; afr[sl][mt][3] = hi.y;
            }
            #pragma unroll
            for (int nt = 0; nt < 8; nt++) {
                float2 bb = *(const float2*)(sB + (wn + nt * 8 + g) * PITCH + kslot);
                bfr[sl][nt][0] = bb.x; bfr[sl][nt][1] = bb.y;
            }
        };

        ldfrag(0, 0);
        #pragma unroll
        for (int ks = 0; ks < 4; ks++) {
            const int cur = ks & 1;
            if (ks < 3) ldfrag(ks + 1, cur ^ 1);   // overlap with MMAs below
            #pragma unroll
            for (int mt = 0; mt < 4; mt++)
                #pragma unroll
                for (int nt = 0; nt < 8; nt++)
                    mma8(acc[mt][nt], afr[cur][mt], bfr[cur][nt]);
        }
    }

    // ---- epilogue ----
    // C frag: c0 (row g, col 2tg), c1 (+1), c2 (row g+8, col 2tg), c3 (+1)
    const int gnw = bn + wn;                 // 64-aligned -> exactly 1 head
    if (mode == 0) {
        const int isK = (gnw < 1024);
        const int h = (gnw & 1023) >> 6;
        float* base = (isK ? g_K : g_V);
        #pragma unroll
        for (int mt = 0; mt < 4; mt++) {
            const int m0 = bm + wm + mt * 16 + g;
            #pragma unroll
            for (int half = 0; half < 2; half++) {
                const int m = m0 + half * 8;
                const int b = m >> 11, s = m & 2047;
                float* dst = base + (size_t)((b * 16 + h) * 2048 + s) * 64;
                #pragma unroll
                for (int nt = 0; nt < 8; nt++) {
                    const int e = nt * 8 + tg * 2;
                    *(float2*)(dst + e) = make_float2(acc[mt][nt][half * 2],
                                                      acc[mt][nt][half * 2 + 1]);
                }
            }
        }
    } else {
        #pragma unroll
        for (int mt = 0; mt < 4; mt++) {
            const int m0 = bm + wm + mt * 16 + g;
            #pragma unroll
            for (int half = 0; half < 2; half++) {
                const int m = m0 + half * 8;
                float* dst = Y + (size_t)m * 1024;
                #pragma unroll
                for (int nt = 0; nt < 8; nt++) {
                    const int gn = gnw + nt * 8 + tg * 2;
                    float2 bb = *(const float2*)(bias + gn);
                    *(float2*)(dst + gn) = make_float2(acc[mt][nt][half * 2] + bb.x,
                                                       acc[mt][nt][half * 2 + 1] + bb.y);
                }
            }
        }
    }
}

// =============================================================
// Kernel 2: per-(b,h) partial M = K^T V over an S-chunk of 256 rows.
// =============================================================
__global__ __launch_bounds__(256) void k2_kv()
{
    const int bh = blockIdx.x;
    const int sc = blockIdx.y;
    const float* K = g_K + (bh * S_LEN + sc * 256) * HS;
    const float* V = g_V + (bh * S_LEN + sc * 256) * HS;

    __shared__ float Ks[32][64];
    __shared__ float Vs[32][64];
    const int tid = threadIdx.x;
    const int tx = tid & 15, ty = tid >> 4;

    float acc[4][4] = {};

    for (int s0 = 0; s0 < 256; s0 += 32) {
        #pragma unroll
        for (int i = 0; i < 2; i++) {
            int idx = (tid + i * 256) * 4;
            int r = idx >> 6, c = idx & 63;
            *(float4*)&Ks[r][c] = *(const float4*)(K + (s0 + r) * HS + c);
            *(float4*)&Vs[r][c] = *(const float4*)(V + (s0 + r) * HS + c);
        }
        __syncthreads();
        #pragma unroll
        for (int s = 0; s < 32; s++) {
            float4 a4 = *(const float4*)&Ks[s][ty * 4];
            float4 b4 = *(const float4*)&Vs[s][tx * 4];
            float a[4] = {a4.x, a4.y, a4.z, a4.w};
            float b[4] = {b4.x, b4.y, b4.z, b4.w};
            #pragma unroll
            for (int i = 0; i < 4; i++)
                #pragma unroll
                for (int j = 0; j < 4; j++)
                    acc[i][j] += a[i] * b[j];
        }
        __syncthreads();
    }

    float* P = g_Mpart + (bh * 8 + sc) * (HS * HS);
    #pragma unroll
    for (int i = 0; i < 4; i++)
        #pragma unroll
        for (int j = 0; j < 4; j++)
            P[(ty * 4 + i) * HS + tx * 4 + j] = acc[i][j];
}

__global__ __launch_bounds__(256) void k2_reduce()
{
    int i = blockIdx.x * 256 + threadIdx.x;
    int bh = i >> 12;
    int o  = i & 4095;
    float s = 0.f;
    #pragma unroll
    for (int c = 0; c < 8; c++)
        s += g_Mpart[(bh * 8 + c) * 4096 + o];
    g_M[i] = s * 0.125f;
}

// =============================================================
// Kernel 3 (tensor): A[b,s,h*64+f] = sum_e V[b,h,s,e] * M[b,h,e,f]
// Epilogue writes k-PERMUTED f columns (g_A feeds GEMM2's k-dim).
// =============================================================
#define K3P 68
__global__ __launch_bounds__(256) void k3_av()
{
    __shared__ float Vs[128][K3P];
    __shared__ float Mt[64][K3P];          // Mt[f][e] = M[e][f]

    const int bh = blockIdx.x;
    const int s0 = blockIdx.y * 128;
    const int tid = threadIdx.x, wid = tid >> 5, lane = tid & 31;
    const int g = lane >> 2, tg = lane & 3;

    const float* Vg = g_V + (size_t)(bh * S_LEN + s0) * HS;
    #pragma unroll
    for (int i = 0; i < 8; i++) {
        int idx = tid + i * 256;
        int r = idx >> 4, c4 = idx & 15;
        float4 v = *(const float4*)(Vg + r * HS + c4 * 4);
        *(float4*)&Vs[r][c4 * 4] = make_float4(f2tf32(v.x), f2tf32(v.y),
                                               f2tf32(v.z), f2tf32(v.w));
    }
    const float* Mg = g_M + bh * 4096;
    #pragma unroll
    for (int i = 0; i < 16; i++) {
        int idx = tid + i * 256;
        int e = idx >> 6, f = idx & 63;
        Mt[f][e] = f2tf32(Mg[idx]);
    }
    __syncthreads();

    const int wm = (wid & 3) * 32;        // 4 warps along s
    const int wn = (wid >> 2) * 32;       // 2 warps along f

    float acc[2][4][4] = {};
    #pragma unroll
    for (int ks = 0; ks < 8; ks++) {
        const int k = ks * 8 + tg;
        float a[2][4], b[4][2];
        #pragma unroll
        for (int mt = 0; mt < 2; mt++) {
            const float* p = &Vs[wm + mt * 16 + g][k];
            a[mt][0] = p[0];
            a[mt][1] = p[8 * K3P];
            a[mt][2] = p[4];
            a[mt][3] = p[8 * K3P + 4];
        }
        #pragma unroll
        for (int nt = 0; nt < 4; nt++) {
            const float* p = &Mt[wn + nt * 8 + g][k];
            b[nt][0] = p[0];
            b[nt][1] = p[4];
        }
        #pragma unroll
        for (int mt = 0; mt < 2; mt++)
            #pragma unroll
            for (int nt = 0; nt < 4; nt++)
                mma8(acc[mt][nt], a[mt], b[nt]);
    }

    const int b = bh >> 4, h = bh & 15;
    #pragma unroll
    for (int mt = 0; mt < 2; mt++) {
        const int r0 = wm + mt * 16 + g;
        #pragma unroll
        for (int half = 0; half < 2; half++) {
            const int s = s0 + r0 + half * 8;
            float* dst = g_A + (size_t)(b * S_LEN + s) * D_DIM + h * HS;
            #pragma unroll
            for (int nt = 0; nt < 4; nt++) {
                const int f = wn + nt * 8 + tg * 2;          // logical
                dst[PERMK(f)]     = f2tf32(acc[mt][nt][half * 2]);
                dst[PERMK(f + 1)] = f2tf32(acc[mt][nt][half * 2 + 1]);
            }
        }
    }
}

// =============================================================
extern "C" void kernel_launch(void* const* d_in, const int* in_sizes, int n_in,
                              void* d_out, int out_size)
{
    const float* x   = (const float*)d_in[0];
    const float* Wk  = (const float*)d_in[1];
    const float* Wv  = (const float*)d_in[2];
    const float* Wp  = (const float*)d_in[3];
    const float* bp  = (const float*)d_in[4];
    float* Y = (float*)d_out;

    cudaFuncSetAttribute(gemm_mma, cudaFuncAttributeMaxDynamicSharedMemorySize, GEMM_SMEM);

    xcvt<<<2048, 256>>>(x);                            // x -> tf32, permuted
    tW  <<<dim3(32, 2, 32), dim3(32, 8)>>>(Wk, Wv);    // [Wk|Wv] -> K-major tf32
    tWp <<<dim3(32, 32),    dim3(32, 8)>>>(Wp);        // Wproj^T -> K-major tf32

    gemm_mma<<<dim3(8, 32), 256, GEMM_SMEM>>>(bp, Y, 0);   // K,V projection
    k2_kv    <<<dim3(32, 8), 256>>>();                     // partial K^T V
    k2_reduce<<<512, 256>>>();                             // reduce + scale
    k3_av    <<<dim3(32, 16), 256>>>();                    // V @ M -> g_A (tensor)
    gemm_mma<<<dim3(4, 32), 256, GEMM_SMEM>>>(bp, Y, 1);   // Y = A@Wp + b
}

// round 11
// speedup vs baseline: 1.6754x; 1.6754x over previous
#include <cuda_runtime.h>
#include <cuda_fp16.h>

// B=2, S=2048, D=1024, H=16, HS=64
// out = V @ (K^T @ V) / 8 per (b,h)   (no softmax, Q==V)
// R11: big GEMMs on fp16 mma.sync.m16n8k16 (same 10-bit mantissa as tf32,
// half the instructions, 2x pipe rate). R10's frag double-buffering reverted
// (it regressed). Pair-permuted fp16 layout -> one LDS.64 per fragment.

#define S_LEN 2048
#define D_DIM 1024
#define HS    64
#define BH    32
#define MROWS 4096

// fp16 pair permutation within each 16-half group: pair order
// [p0,p4,p1,p5,p2,p6,p3,p7] -> fragment pairs (tg, tg+4) adjacent (LDS.64).
__device__ __forceinline__ int permh(int k) {
    int grp = k & ~15, kk = k & 15, pr = kk >> 1, od = kk & 1;
    int s = (pr < 4) ? (2 * pr) : (2 * (pr - 4) + 1);
    return grp + 2 * s + od;
}

// ---------------- scratch (no allocs allowed) ----------------
__device__ float  g_K[BH * S_LEN * HS];        // [B,H,S,HS] fp32
__device__ float  g_V[BH * S_LEN * HS];        // [B,H,S,HS] fp32
__device__ float  g_Mpart[BH * 8 * HS * HS];
__device__ float  g_M[BH * HS * HS];
__device__ __half g_Ah[MROWS * D_DIM];         // concat heads, fp16 permuted
__device__ __half g_Xh[MROWS * D_DIM];         // x fp16 permuted
__device__ __half g_Wth[2048 * 1024];          // [Wk|Wv] K-major, permuted
__device__ __half g_Wpth[1024 * 1024];         // Wproj^T K-major, permuted

// =============================================================
// helpers
// =============================================================
__device__ __forceinline__ float f2tf32(float f) {
    unsigned u;
    asm("cvt.rna.tf32.f32 %0, %1;" : "=r"(u) : "f"(f));
    return __uint_as_float(u);
}

__device__ __forceinline__ void cp16(void* dst, const void* src) {
    unsigned d;
    asm("{ .reg .u64 t; cvta.to.shared.u64 t, %1; cvt.u32.u64 %0, t; }"
        : "=r"(d) : "l"(dst));
    asm volatile("cp.async.cg.shared.global [%0], [%1], 16;" :: "r"(d), "l"(src));
}

__device__ __forceinline__ void mma16(float* d, const unsigned* a, const unsigned* b) {
    asm volatile(
        "mma.sync.aligned.m16n8k16.row.col.f32.f16.f16.f32 "
        "{%0,%1,%2,%3}, {%4,%5,%6,%7}, {%8,%9}, {%0,%1,%2,%3};"
        : "+f"(d[0]), "+f"(d[1]), "+f"(d[2]), "+f"(d[3])
        : "r"(a[0]), "r"(a[1]), "r"(a[2]), "r"(a[3]), "r"(b[0]), "r"(b[1]));
}

// tf32 mma (kept for k3)
__device__ __forceinline__ void mma8(float* d, const float* a, const float* b) {
    asm volatile(
        "mma.sync.aligned.m16n8k8.row.col.f32.tf32.tf32.f32 "
        "{%0,%1,%2,%3}, {%4,%5,%6,%7}, {%8,%9}, {%0,%1,%2,%3};"
        : "+f"(d[0]), "+f"(d[1]), "+f"(d[2]), "+f"(d[3])
        : "r"(__float_as_uint(a[0])), "r"(__float_as_uint(a[1])),
          "r"(__float_as_uint(a[2])), "r"(__float_as_uint(a[3])),
          "r"(__float_as_uint(b[0])), "r"(__float_as_uint(b[1])));
}

// =============================================================
// x -> fp16, pair-permuted. One thread per 16-half group.
// =============================================================
__global__ __launch_bounds__(256) void xcvt(const float* __restrict__ x)
{
    int base = (blockIdx.x * 256 + threadIdx.x) * 16;
    float v[16];
    #pragma unroll
    for (int i = 0; i < 4; i++)
        *(float4*)(v + 4 * i) = *(const float4*)(x + base + 4 * i);
    __half2 out[8];
    #pragma unroll
    for (int p = 0; p < 8; p++) {
        int s = (p < 4) ? (2 * p) : (2 * (p - 4) + 1);
        out[s] = __floats2half2_rn(v[2 * p], v[2 * p + 1]);
    }
    *(uint4*)(g_Xh + base)     = ((uint4*)out)[0];
    *(uint4*)(g_Xh + base + 8) = ((uint4*)out)[1];
}

// =============================================================
// Weight transposes -> K-major rows, fp16, pair-permuted columns
// =============================================================
__global__ __launch_bounds__(256) void tW(const float* __restrict__ Wk,
                                          const float* __restrict__ Wv)
{
    __shared__ float tile[32][33];
    const int hh = blockIdx.z;
    const int x0 = blockIdx.x * 32;         // d tile (k-dim)
    const int y0 = blockIdx.y * 32;         // e tile
    const int tx = threadIdx.x, ty = threadIdx.y;
    const float* W = (hh < 16) ? Wk : Wv;
    const int h = hh & 15;
    #pragma unroll
    for (int j = 0; j < 4; j++)
        tile[ty + 8 * j][tx] = W[h * 65536 + (x0 + ty + 8 * j) * 64 + y0 + tx];
    __syncthreads();
    const int dp = x0 + permh(tx);
    #pragma unroll
    for (int j = 0; j < 4; j++)
        g_Wth[(hh * 64 + y0 + ty + 8 * j) * 1024 + dp] =
            __float2half_rn(tile[tx][ty + 8 * j]);
}

__global__ __launch_bounds__(256) void tWp(const float* __restrict__ Wp)
{
    __shared__ float tile[32][33];
    const int x0 = blockIdx.x * 32;   // n tile
    const int y0 = blockIdx.y * 32;   // k tile
    const int tx = threadIdx.x, ty = threadIdx.y;
    #pragma unroll
    for (int j = 0; j < 4; j++)
        tile[ty + 8 * j][tx] = Wp[(y0 + ty + 8 * j) * 1024 + x0 + tx];
    __syncthreads();
    const int kp = y0 + permh(tx);
    #pragma unroll
    for (int j = 0; j < 4; j++)
        g_Wpth[(x0 + ty + 8 * j) * 1024 + kp] =
            __float2half_rn(tile[tx][ty + 8 * j]);
}

// =============================================================
// fp16 mma.sync GEMM: C[4096, N] = A[4096,1024] @ B^T (B = K-major rows)
// BM=128, BN=256, BK=64 halves, 3-stage / distance-2 prefetch, one sync/iter.
// Row pitch 160B (==32B mod 128) -> LDS.64 frags conflict-free per phase.
// mode 0: A=g_Xh, B=g_Wth, scatter K/V (fp32). mode 1: A=g_Ah, B=g_Wpth, Y.
// =============================================================
#define BMt 128
#define BNt 256
#define BKh 64                                  // halves per k-chunk
#define PITCHB 160                              // bytes per smem row
#define SA_BYTES (BMt * PITCHB)                 // 20480
#define SB_BYTES (BNt * PITCHB)                 // 40960
#define STAGE_BYTES (SA_BYTES + SB_BYTES)       // 61440
#define GEMM_SMEM (3 * STAGE_BYTES)             // 184320

__global__ __launch_bounds__(256, 1)
void gemm_mma(const float* __restrict__ bias,
              float* __restrict__ Y,
              int mode)
{
    extern __shared__ __align__(16) char sm[];
    const int tid = threadIdx.x, wid = tid >> 5, lane = tid & 31;
    const int g = lane >> 2, tg = lane & 3;
    const int bm = blockIdx.y * BMt, bn = blockIdx.x * BNt;

    const __half* Ag = ((mode == 0) ? g_Xh : g_Ah) + (size_t)bm * 1024;
    const __half* Bg = ((mode == 0) ? g_Wth : g_Wpth) + (size_t)bn * 1024;

    auto prefetch = [&](int kc) {
        char* sA = sm + (kc % 3) * STAGE_BYTES;
        char* sB = sA + SA_BYTES;
        const __half* As = Ag + kc * BKh;
        const __half* Bs = Bg + kc * BKh;
        #pragma unroll
        for (int i = 0; i < 4; i++) {           // A: 128 rows x 8 chunks
            int idx = tid + i * 256;
            int m = idx >> 3, c8 = idx & 7;
            cp16(sA + m * PITCHB + c8 * 16, As + (size_t)m * 1024 + c8 * 8);
        }
        #pragma unroll
        for (int i = 0; i < 8; i++) {           // B: 256 rows x 8 chunks
            int idx = tid + i * 256;
            int n = idx >> 3, c8 = idx & 7;
            cp16(sB + n * PITCHB + c8 * 16, Bs + (size_t)n * 1024 + c8 * 8);
        }
        asm volatile("cp.async.commit_group;" ::: "memory");
    };

    prefetch(0); prefetch(1);

    const int wm = (wid & 1) * 64;       // 2 warps along M
    const int wn = (wid >> 1) * 64;      // 4 warps along N

    float acc[4][8][4];
    #pragma unroll
    for (int mt = 0; mt < 4; mt++)
        #pragma unroll
        for (int nt = 0; nt < 8; nt++)
            #pragma unroll
            for (int q = 0; q < 4; q++) acc[mt][nt][q] = 0.f;

    for (int kc = 0; kc < 16; kc++) {
        const char* sA = sm + (kc % 3) * STAGE_BYTES;
        const char* sB = sA + SA_BYTES;
        if (kc < 15) asm volatile("cp.async.wait_group 1;" ::: "memory");
        else         asm volatile("cp.async.wait_group 0;" ::: "memory");
        __syncthreads();
        if (kc + 2 < 16) prefetch(kc + 2);

        #pragma unroll
        for (int ks = 0; ks < 4; ks++) {        // 4 x k16 per chunk
            const int koff = ks * 32 + 8 * tg;  // bytes: slot pair (tg, tg+4)
            unsigned a[4][4], b[8][2];
            #pragma unroll
            for (int mt = 0; mt < 4; mt++) {
                const char* p = sA + (wm + mt * 16 + g) * PITCHB + koff;
                uint2 lo = *(const uint2*)p;                  // row g
                uint2 hi = *(const uint2*)(p + 8 * PITCHB);   // row g+8
                a[mt][0] = lo.x; a[mt][1] = hi.x;             // k-lo pairs
                a[mt][2] = lo.y; a[mt][3] = hi.y;             // k-hi pairs
            }
            #pragma unroll
            for (int nt = 0; nt < 8; nt++) {
                uint2 bb = *(const uint2*)(sB + (wn + nt * 8 + g) * PITCHB + koff);
                b[nt][0] = bb.x; b[nt][1] = bb.y;
            }
            #pragma unroll
            for (int mt = 0; mt < 4; mt++)
                #pragma unroll
                for (int nt = 0; nt < 8; nt++)
                    mma16(acc[mt][nt], a[mt], b[nt]);
        }
    }

    // ---- epilogue ----
    // C frag: c0 (row g, col 2tg), c1 (+1), c2 (row g+8, col 2tg), c3 (+1)
    const int gnw = bn + wn;                 // 64-aligned -> exactly 1 head
    if (mode == 0) {
        const int isK = (gnw < 1024);
        const int h = (gnw & 1023) >> 6;
        float* base = (isK ? g_K : g_V);
        #pragma unroll
        for (int mt = 0; mt < 4; mt++) {
            const int m0 = bm + wm + mt * 16 + g;
            #pragma unroll
            for (int half = 0; half < 2; half++) {
                const int m = m0 + half * 8;
                const int b = m >> 11, s = m & 2047;
                float* dst = base + (size_t)((b * 16 + h) * 2048 + s) * 64;
                #pragma unroll
                for (int nt = 0; nt < 8; nt++) {
                    const int e = nt * 8 + tg * 2;
                    *(float2*)(dst + e) = make_float2(acc[mt][nt][half * 2],
                                                      acc[mt][nt][half * 2 + 1]);
                }
            }
        }
    } else {
        #pragma unroll
        for (int mt = 0; mt < 4; mt++) {
            const int m0 = bm + wm + mt * 16 + g;
            #pragma unroll
            for (int half = 0; half < 2; half++) {
                const int m = m0 + half * 8;
                float* dst = Y + (size_t)m * 1024;
                #pragma unroll
                for (int nt = 0; nt < 8; nt++) {
                    const int gn = gnw + nt * 8 + tg * 2;
                    float2 bb = *(const float2*)(bias + gn);
                    *(float2*)(dst + gn) = make_float2(acc[mt][nt][half * 2] + bb.x,
                                                       acc[mt][nt][half * 2 + 1] + bb.y);
                }
            }
        }
    }
}

// =============================================================
// Kernel 2: per-(b,h) partial M = K^T V over an S-chunk of 256 rows. (fp32)
// =============================================================
__global__ __launch_bounds__(256) void k2_kv()
{
    const int bh = blockIdx.x;
    const int sc = blockIdx.y;
    const float* K = g_K + (bh * S_LEN + sc * 256) * HS;
    const float* V = g_V + (bh * S_LEN + sc * 256) * HS;

    __shared__ float Ks[32][64];
    __shared__ float Vs[32][64];
    const int tid = threadIdx.x;
    const int tx = tid & 15, ty = tid >> 4;

    float acc[4][4] = {};

    for (int s0 = 0; s0 < 256; s0 += 32) {
        #pragma unroll
        for (int i = 0; i < 2; i++) {
            int idx = (tid + i * 256) * 4;
            int r = idx >> 6, c = idx & 63;
            *(float4*)&Ks[r][c] = *(const float4*)(K + (s0 + r) * HS + c);
            *(float4*)&Vs[r][c] = *(const float4*)(V + (s0 + r) * HS + c);
        }
        __syncthreads();
        #pragma unroll
        for (int s = 0; s < 32; s++) {
            float4 a4 = *(const float4*)&Ks[s][ty * 4];
            float4 b4 = *(const float4*)&Vs[s][tx * 4];
            float a[4] = {a4.x, a4.y, a4.z, a4.w};
            float b[4] = {b4.x, b4.y, b4.z, b4.w};
            #pragma unroll
            for (int i = 0; i < 4; i++)
                #pragma unroll
                for (int j = 0; j < 4; j++)
                    acc[i][j] += a[i] * b[j];
        }
        __syncthreads();
    }

    float* P = g_Mpart + (bh * 8 + sc) * (HS * HS);
    #pragma unroll
    for (int i = 0; i < 4; i++)
        #pragma unroll
        for (int j = 0; j < 4; j++)
            P[(ty * 4 + i) * HS + tx * 4 + j] = acc[i][j];
}

__global__ __launch_bounds__(256) void k2_reduce()
{
    int i = blockIdx.x * 256 + threadIdx.x;
    int bh = i >> 12;
    int o  = i & 4095;
    float s = 0.f;
    #pragma unroll
    for (int c = 0; c < 8; c++)
        s += g_Mpart[(bh * 8 + c) * 4096 + o];
    g_M[i] = s * 0.125f;
}

// =============================================================
// Kernel 3 (tensor, tf32): A[b,s,h*64+f] = sum_e V[b,h,s,e] * M[b,h,e,f]
// Epilogue writes fp16 pair-PERMUTED f columns into g_Ah (GEMM2's k-dim).
// =============================================================
#define K3P 68
__global__ __launch_bounds__(256) void k3_av()
{
    __shared__ float Vs[128][K3P];
    __shared__ float Mt[64][K3P];          // Mt[f][e] = M[e][f]

    const int bh = blockIdx.x;
    const int s0 = blockIdx.y * 128;
    const int tid = threadIdx.x, wid = tid >> 5, lane = tid & 31;
    const int g = lane >> 2, tg = lane & 3;

    const float* Vg = g_V + (size_t)(bh * S_LEN + s0) * HS;
    #pragma unroll
    for (int i = 0; i < 8; i++) {
        int idx = tid + i * 256;
        int r = idx >> 4, c4 = idx & 15;
        float4 v = *(const float4*)(Vg + r * HS + c4 * 4);
        *(float4*)&Vs[r][c4 * 4] = make_float4(f2tf32(v.x), f2tf32(v.y),
                                               f2tf32(v.z), f2tf32(v.w));
    }
    const float* Mg = g_M + bh * 4096;
    #pragma unroll
    for (int i = 0; i < 16; i++) {
        int idx = tid + i * 256;
        int e = idx >> 6, f = idx & 63;
        Mt[f][e] = f2tf32(Mg[idx]);
    }
    __syncthreads();

    const int wm = (wid & 3) * 32;        // 4 warps along s
    const int wn = (wid >> 2) * 32;       // 2 warps along f

    float acc[2][4][4] = {};
    #pragma unroll
    for (int ks = 0; ks < 8; ks++) {
        const int k = ks * 8 + tg;
        float a[2][4], b[4][2];
        #pragma unroll
        for (int mt = 0; mt < 2; mt++) {
            const float* p = &Vs[wm + mt * 16 + g][k];
            a[mt][0] = p[0];
            a[mt][1] = p[8 * K3P];
            a[mt][2] = p[4];
            a[mt][3] = p[8 * K3P + 4];
        }
        #pragma unroll
        for (int nt = 0; nt < 4; nt++) {
            const float* p = &Mt[wn + nt * 8 + g][k];
            b[nt][0] = p[0];
            b[nt][1] = p[4];
        }
        #pragma unroll
        for (int mt = 0; mt < 2; mt++)
            #pragma unroll
            for (int nt = 0; nt < 4; nt++)
                mma8(acc[mt][nt], a[mt], b[nt]);
    }

    const int b = bh >> 4, h = bh & 15;
    #pragma unroll
    for (int mt = 0; mt < 2; mt++) {
        const int r0 = wm + mt * 16 + g;
        #pragma unroll
        for (int half = 0; half < 2; half++) {
            const int s = s0 + r0 + half * 8;
            __half* dst = g_Ah + (size_t)(b * S_LEN + s) * D_DIM + h * HS;
            #pragma unroll
            for (int nt = 0; nt < 4; nt++) {
                const int f = wn + nt * 8 + tg * 2;          // logical, even
                dst[permh(f)]     = __float2half_rn(acc[mt][nt][half * 2]);
                dst[permh(f + 1)] = __float2half_rn(acc[mt][nt][half * 2 + 1]);
            }
        }
    }
}

// =============================================================
extern "C" void kernel_launch(void* const* d_in, const int* in_sizes, int n_in,
                              void* d_out, int out_size)
{
    const float* x   = (const float*)d_in[0];
    const float* Wk  = (const float*)d_in[1];
    const float* Wv  = (const float*)d_in[2];
    const float* Wp  = (const float*)d_in[3];
    const float* bp  = (const float*)d_in[4];
    float* Y = (float*)d_out;

    cudaFuncSetAttribute(gemm_mma, cudaFuncAttributeMaxDynamicSharedMemorySize, GEMM_SMEM);

    xcvt<<<1024, 256>>>(x);                            // x -> fp16, permuted
    tW  <<<dim3(32, 2, 32), dim3(32, 8)>>>(Wk, Wv);    // [Wk|Wv] -> K-major fp16
    tWp <<<dim3(32, 32),    dim3(32, 8)>>>(Wp);        // Wproj^T -> K-major fp16

    gemm_mma<<<dim3(8, 32), 256, GEMM_SMEM>>>(bp, Y, 0);   // K,V projection
    k2_kv    <<<dim3(32, 8), 256>>>();                     // partial K^T V
    k2_reduce<<<512, 256>>>();                             // reduce + scale
    k3_av    <<<dim3(32, 16), 256>>>();                    // V @ M -> g_Ah
    gemm_mma<<<dim3(4, 32), 256, GEMM_SMEM>>>(bp, Y, 1);   // Y = A@Wp + b
}

// round 12
// speedup vs baseline: 1.7458x; 1.0421x over previous
#include <cuda_runtime.h>
#include <cuda_fp16.h>

// B=2, S=2048, D=1024, H=16, HS=64
// out = V @ (K^T @ V) / 8 per (b,h)   (no softmax, Q==V)
// R12: tail attack. K/V stored fp16-only (halves epilogue+k2+k3 traffic;
// fp16 mantissa == tf32 mantissa so error ~unchanged), k2_reduce folded into
// k2 via atomicAdd (g_M zeroed in prep), xcvt/tW/tWp/zero fused into one
// prep kernel. GEMM inner loops untouched from the R11 win.

#define S_LEN 2048
#define D_DIM 1024
#define HS    64
#define BH    32
#define MROWS 4096

// fp16 pair permutation within each 16-half group: pair order
// [p0,p4,p1,p5,p2,p6,p3,p7] -> fragment pairs (tg, tg+4) adjacent (LDS.64).
__device__ __forceinline__ int permh(int k) {
    int grp = k & ~15, kk = k & 15, pr = kk >> 1, od = kk & 1;
    int s = (pr < 4) ? (2 * pr) : (2 * (pr - 4) + 1);
    return grp + 2 * s + od;
}

// ---------------- scratch (no allocs allowed) ----------------
__device__ __half g_Kh[BH * S_LEN * HS];       // [B,H,S,HS] fp16
__device__ __half g_Vh[BH * S_LEN * HS];       // [B,H,S,HS] fp16
__device__ float  g_M[BH * HS * HS];           // K^T V / 8 (atomic accum)
__device__ __half g_Ah[MROWS * D_DIM];         // concat heads, fp16 permuted
__device__ __half g_Xh[MROWS * D_DIM];         // x fp16 permuted
__device__ __half g_Wth[2048 * 1024];          // [Wk|Wv] K-major, permuted
__device__ __half g_Wpth[1024 * 1024];         // Wproj^T K-major, permuted

// =============================================================
// helpers
// =============================================================
__device__ __forceinline__ float f2tf32(float f) {
    unsigned u;
    asm("cvt.rna.tf32.f32 %0, %1;" : "=r"(u) : "f"(f));
    return __uint_as_float(u);
}

__device__ __forceinline__ void cp16(void* dst, const void* src) {
    unsigned d;
    asm("{ .reg .u64 t; cvta.to.shared.u64 t, %1; cvt.u32.u64 %0, t; }"
        : "=r"(d) : "l"(dst));
    asm volatile("cp.async.cg.shared.global [%0], [%1], 16;" :: "r"(d), "l"(src));
}

__device__ __forceinline__ void mma16(float* d, const unsigned* a, const unsigned* b) {
    asm volatile(
        "mma.sync.aligned.m16n8k16.row.col.f32.f16.f16.f32 "
        "{%0,%1,%2,%3}, {%4,%5,%6,%7}, {%8,%9}, {%0,%1,%2,%3};"
        : "+f"(d[0]), "+f"(d[1]), "+f"(d[2]), "+f"(d[3])
        : "r"(a[0]), "r"(a[1]), "r"(a[2]), "r"(a[3]), "r"(b[0]), "r"(b[1]));
}

// tf32 mma (k3)
__device__ __forceinline__ void mma8(float* d, const float* a, const float* b) {
    asm volatile(
        "mma.sync.aligned.m16n8k8.row.col.f32.tf32.tf32.f32 "
        "{%0,%1,%2,%3}, {%4,%5,%6,%7}, {%8,%9}, {%0,%1,%2,%3};"
        : "+f"(d[0]), "+f"(d[1]), "+f"(d[2]), "+f"(d[3])
        : "r"(__float_as_uint(a[0])), "r"(__float_as_uint(a[1])),
          "r"(__float_as_uint(a[2])), "r"(__float_as_uint(a[3])),
          "r"(__float_as_uint(b[0])), "r"(__float_as_uint(b[1])));
}

// =============================================================
// prep: fused xcvt + tW + tWp + g_M zeroing, dispatched by block range.
//  [0,1024)      x -> fp16 permuted
//  [1024,3072)   [Wk|Wv] -> K-major fp16 permuted
//  [3072,4096)   Wproj^T -> K-major fp16 permuted
//  [4096,4608)   g_M = 0
// =============================================================
__global__ __launch_bounds__(256) void prep(const float* __restrict__ x,
                                            const float* __restrict__ Wk,
                                            const float* __restrict__ Wv,
                                            const float* __restrict__ Wp)
{
    __shared__ float tile[32][33];
    const int blk = blockIdx.x, tid = threadIdx.x;

    if (blk < 1024) {                       // ---- xcvt ----
        int base = (blk * 256 + tid) * 16;
        float v[16];
        #pragma unroll
        for (int i = 0; i < 4; i++)
            *(float4*)(v + 4 * i) = *(const float4*)(x + base + 4 * i);
        __half2 out[8];
        #pragma unroll
        for (int p = 0; p < 8; p++) {
            int s = (p < 4) ? (2 * p) : (2 * (p - 4) + 1);
            out[s] = __floats2half2_rn(v[2 * p], v[2 * p + 1]);
        }
        *(uint4*)(g_Xh + base)     = ((uint4*)out)[0];
        *(uint4*)(g_Xh + base + 8) = ((uint4*)out)[1];
    } else if (blk < 3072) {                // ---- tW ----
        const int local = blk - 1024;
        const int bx = local & 31, by = (local >> 5) & 1, hh = local >> 6;
        const int x0 = bx * 32, y0 = by * 32;
        const int tx = tid & 31, ty = tid >> 5;
        const float* W = (hh < 16) ? Wk : Wv;
        const int h = hh & 15;
        #pragma unroll
        for (int j = 0; j < 4; j++)
            tile[ty + 8 * j][tx] = W[h * 65536 + (x0 + ty + 8 * j) * 64 + y0 + tx];
        __syncthreads();
        const int dp = x0 + permh(tx);
        #pragma unroll
        for (int j = 0; j < 4; j++)
            g_Wth[(hh * 64 + y0 + ty + 8 * j) * 1024 + dp] =
                __float2half_rn(tile[tx][ty + 8 * j]);
    } else if (blk < 4096) {                // ---- tWp ----
        const int local = blk - 3072;
        const int bx = local & 31, by = local >> 5;
        const int x0 = bx * 32, y0 = by * 32;
        const int tx = tid & 31, ty = tid >> 5;
        #pragma unroll
        for (int j = 0; j < 4; j++)
            tile[ty + 8 * j][tx] = Wp[(y0 + ty + 8 * j) * 1024 + x0 + tx];
        __syncthreads();
        const int kp = y0 + permh(tx);
        #pragma unroll
        for (int j = 0; j < 4; j++)
            g_Wpth[(x0 + ty + 8 * j) * 1024 + kp] =
                __float2half_rn(tile[tx][ty + 8 * j]);
    } else {                                // ---- zero g_M ----
        g_M[(blk - 4096) * 256 + tid] = 0.f;
    }
}

// =============================================================
// fp16 mma.sync GEMM: C[4096, N] = A[4096,1024] @ B^T (B = K-major rows)
// BM=128, BN=256, BK=64 halves, 3-stage / distance-2 prefetch, one sync/iter.
// mode 0: A=g_Xh, B=g_Wth, scatter K/V (fp16). mode 1: A=g_Ah, B=g_Wpth, Y.
// =============================================================
#define BMt 128
#define BNt 256
#define BKh 64                                  // halves per k-chunk
#define PITCHB 160                              // bytes per smem row
#define SA_BYTES (BMt * PITCHB)                 // 20480
#define SB_BYTES (BNt * PITCHB)                 // 40960
#define STAGE_BYTES (SA_BYTES + SB_BYTES)       // 61440
#define GEMM_SMEM (3 * STAGE_BYTES)             // 184320

__global__ __launch_bounds__(256, 1)
void gemm_mma(const float* __restrict__ bias,
              float* __restrict__ Y,
              int mode)
{
    extern __shared__ __align__(16) char sm[];
    const int tid = threadIdx.x, wid = tid >> 5, lane = tid & 31;
    const int g = lane >> 2, tg = lane & 3;
    const int bm = blockIdx.y * BMt, bn = blockIdx.x * BNt;

    const __half* Ag = ((mode == 0) ? g_Xh : g_Ah) + (size_t)bm * 1024;
    const __half* Bg = ((mode == 0) ? g_Wth : g_Wpth) + (size_t)bn * 1024;

    auto prefetch = [&](int kc) {
        char* sA = sm + (kc % 3) * STAGE_BYTES;
        char* sB = sA + SA_BYTES;
        const __half* As = Ag + kc * BKh;
        const __half* Bs = Bg + kc * BKh;
        #pragma unroll
        for (int i = 0; i < 4; i++) {           // A: 128 rows x 8 chunks
            int idx = tid + i * 256;
            int m = idx >> 3, c8 = idx & 7;
            cp16(sA + m * PITCHB + c8 * 16, As + (size_t)m * 1024 + c8 * 8);
        }
        #pragma unroll
        for (int i = 0; i < 8; i++) {           // B: 256 rows x 8 chunks
            int idx = tid + i * 256;
            int n = idx >> 3, c8 = idx & 7;
            cp16(sB + n * PITCHB + c8 * 16, Bs + (size_t)n * 1024 + c8 * 8);
        }
        asm volatile("cp.async.commit_group;" ::: "memory");
    };

    prefetch(0); prefetch(1);

    const int wm = (wid & 1) * 64;       // 2 warps along M
    const int wn = (wid >> 1) * 64;      // 4 warps along N

    float acc[4][8][4];
    #pragma unroll
    for (int mt = 0; mt < 4; mt++)
        #pragma unroll
        for (int nt = 0; nt < 8; nt++)
            #pragma unroll
            for (int q = 0; q < 4; q++) acc[mt][nt][q] = 0.f;

    for (int kc = 0; kc < 16; kc++) {
        const char* sA = sm + (kc % 3) * STAGE_BYTES;
        const char* sB = sA + SA_BYTES;
        if (kc < 15) asm volatile("cp.async.wait_group 1;" ::: "memory");
        else         asm volatile("cp.async.wait_group 0;" ::: "memory");
        __syncthreads();
        if (kc + 2 < 16) prefetch(kc + 2);

        #pragma unroll
        for (int ks = 0; ks < 4; ks++) {        // 4 x k16 per chunk
            const int koff = ks * 32 + 8 * tg;  // bytes: slot pair (tg, tg+4)
            unsigned a[4][4], b[8][2];
            #pragma unroll
            for (int mt = 0; mt < 4; mt++) {
                const char* p = sA + (wm + mt * 16 + g) * PITCHB + koff;
                uint2 lo = *(const uint2*)p;                  // row g
                uint2 hi = *(const uint2*)(p + 8 * PITCHB);   // row g+8
                a[mt][0] = lo.x; a[mt][1] = hi.x;
                a[mt][2] = lo.y; a[mt][3] = hi.y;
            }
            #pragma unroll
            for (int nt = 0; nt < 8; nt++) {
                uint2 bb = *(const uint2*)(sB + (wn + nt * 8 + g) * PITCHB + koff);
                b[nt][0] = bb.x; b[nt][1] = bb.y;
            }
            #pragma unroll
            for (int mt = 0; mt < 4; mt++)
                #pragma unroll
                for (int nt = 0; nt < 8; nt++)
                    mma16(acc[mt][nt], a[mt], b[nt]);
        }
    }

    // ---- epilogue ----
    // C frag: c0 (row g, col 2tg), c1 (+1), c2 (row g+8, col 2tg), c3 (+1)
    const int gnw = bn + wn;                 // 64-aligned -> exactly 1 head
    if (mode == 0) {
        const int isK = (gnw < 1024);
        const int h = (gnw & 1023) >> 6;
        __half* base = (isK ? g_Kh : g_Vh);
        #pragma unroll
        for (int mt = 0; mt < 4; mt++) {
            const int m0 = bm + wm + mt * 16 + g;
            #pragma unroll
            for (int half = 0; half < 2; half++) {
                const int m = m0 + half * 8;
                const int b = m >> 11, s = m & 2047;
                __half* dst = base + (size_t)((b * 16 + h) * 2048 + s) * 64;
                #pragma unroll
                for (int nt = 0; nt < 8; nt++) {
                    const int e = nt * 8 + tg * 2;
                    *(__half2*)(dst + e) =
                        __floats2half2_rn(acc[mt][nt][half * 2],
                                          acc[mt][nt][half * 2 + 1]);
                }
            }
        }
    } else {
        #pragma unroll
        for (int mt = 0; mt < 4; mt++) {
            const int m0 = bm + wm + mt * 16 + g;
            #pragma unroll
            for (int half = 0; half < 2; half++) {
                const int m = m0 + half * 8;
                float* dst = Y + (size_t)m * 1024;
                #pragma unroll
                for (int nt = 0; nt < 8; nt++) {
                    const int gn = gnw + nt * 8 + tg * 2;
                    float2 bb = *(const float2*)(bias + gn);
                    *(float2*)(dst + gn) = make_float2(acc[mt][nt][half * 2] + bb.x,
                                                       acc[mt][nt][half * 2 + 1] + bb.y);
                }
            }
        }
    }
}

// =============================================================
// Kernel 2: per-(b,h) partial M = K^T V over an S-chunk of 256 rows.
// fp16 K,V inputs (converted to fp32 in staging); atomicAdd into g_M
// with the 1/8 scale folded in (g_M zeroed by prep).
// =============================================================
__global__ __launch_bounds__(256) void k2_kv()
{
    const int bh = blockIdx.x;
    const int sc = blockIdx.y;
    const __half* K = g_Kh + (size_t)(bh * S_LEN + sc * 256) * HS;
    const __half* V = g_Vh + (size_t)(bh * S_LEN + sc * 256) * HS;

    __shared__ float Ks[32][64];
    __shared__ float Vs[32][64];
    const int tid = threadIdx.x;
    const int tx = tid & 15, ty = tid >> 4;

    float acc[4][4] = {};

    for (int s0 = 0; s0 < 256; s0 += 32) {
        {
            int idx = tid * 8;                   // 2048 halves per array
            int r = idx >> 6, c = idx & 63;
            uint4 kr = *(const uint4*)(K + (s0 + r) * HS + c);
            uint4 vr = *(const uint4*)(V + (s0 + r) * HS + c);
            const __half2* kh = (const __half2*)&kr;
            const __half2* vh = (const __half2*)&vr;
            #pragma unroll
            for (int q = 0; q < 4; q++) {
                float2 kf = __half22float2(kh[q]);
                float2 vf = __half22float2(vh[q]);
                Ks[r][c + 2 * q] = kf.x; Ks[r][c + 2 * q + 1] = kf.y;
                Vs[r][c + 2 * q] = vf.x; Vs[r][c + 2 * q + 1] = vf.y;
            }
        }
        __syncthreads();
        #pragma unroll
        for (int s = 0; s < 32; s++) {
            float4 a4 = *(const float4*)&Ks[s][ty * 4];
            float4 b4 = *(const float4*)&Vs[s][tx * 4];
            float a[4] = {a4.x, a4.y, a4.z, a4.w};
            float b[4] = {b4.x, b4.y, b4.z, b4.w};
            #pragma unroll
            for (int i = 0; i < 4; i++)
                #pragma unroll
                for (int j = 0; j < 4; j++)
                    acc[i][j] += a[i] * b[j];
        }
        __syncthreads();
    }

    float* Mb = g_M + bh * 4096;
    #pragma unroll
    for (int i = 0; i < 4; i++)
        #pragma unroll
        for (int j = 0; j < 4; j++)
            atomicAdd(&Mb[(ty * 4 + i) * 64 + tx * 4 + j], acc[i][j] * 0.125f);
}

// =============================================================
// Kernel 3 (tensor, tf32): A[b,s,h*64+f] = sum_e V[b,h,s,e] * M[b,h,e,f]
// V staged from fp16 (values already 10-bit mantissa). Epilogue writes
// fp16 pair-PERMUTED f columns into g_Ah (GEMM2's k-dim).
// =============================================================
#define K3P 68
__global__ __launch_bounds__(256) void k3_av()
{
    __shared__ float Vs[128][K3P];
    __shared__ float Mt[64][K3P];          // Mt[f][e] = M[e][f]

    const int bh = blockIdx.x;
    const int s0 = blockIdx.y * 128;
    const int tid = threadIdx.x, wid = tid >> 5, lane = tid & 31;
    const int g = lane >> 2, tg = lane & 3;

    const __half* Vg = g_Vh + (size_t)(bh * S_LEN + s0) * HS;
    #pragma unroll
    for (int i = 0; i < 4; i++) {
        int idx = (tid + i * 256) * 8;       // 8192 halves
        int r = idx >> 6, c = idx & 63;
        uint4 vr = *(const uint4*)(Vg + r * HS + c);
        const __half2* vh = (const __half2*)&vr;
        #pragma unroll
        for (int q = 0; q < 4; q++) {
            float2 vf = __half22float2(vh[q]);
            Vs[r][c + 2 * q] = vf.x; Vs[r][c + 2 * q + 1] = vf.y;
        }
    }
    const float* Mg = g_M + bh * 4096;
    #pragma unroll
    for (int i = 0; i < 16; i++) {
        int idx = tid + i * 256;
        int e = idx >> 6, f = idx & 63;
        Mt[f][e] = f2tf32(Mg[idx]);
    }
    __syncthreads();

    const int wm = (wid & 3) * 32;        // 4 warps along s
    const int wn = (wid >> 2) * 32;       // 2 warps along f

    float acc[2][4][4] = {};
    #pragma unroll
    for (int ks = 0; ks < 8; ks++) {
        const int k = ks * 8 + tg;
        float a[2][4], b[4][2];
        #pragma unroll
        for (int mt = 0; mt < 2; mt++) {
            const float* p = &Vs[wm + mt * 16 + g][k];
            a[mt][0] = p[0];
            a[mt][1] = p[8 * K3P];
            a[mt][2] = p[4];
            a[mt][3] = p[8 * K3P + 4];
        }
        #pragma unroll
        for (int nt = 0; nt < 4; nt++) {
            const float* p = &Mt[wn + nt * 8 + g][k];
            b[nt][0] = p[0];
            b[nt][1] = p[4];
        }
        #pragma unroll
        for (int mt = 0; mt < 2; mt++)
            #pragma unroll
            for (int nt = 0; nt < 4; nt++)
                mma8(acc[mt][nt], a[mt], b[nt]);
    }

    const int b = bh >> 4, h = bh & 15;
    #pragma unroll
    for (int mt = 0; mt < 2; mt++) {
        const int r0 = wm + mt * 16 + g;
        #pragma unroll
        for (int half = 0; half < 2; half++) {
            const int s = s0 + r0 + half * 8;
            __half* dst = g_Ah + (size_t)(b * S_LEN + s) * D_DIM + h * HS;
            #pragma unroll
            for (int nt = 0; nt < 4; nt++) {
                const int f = wn + nt * 8 + tg * 2;          // logical, even
                dst[permh(f)]     = __float2half_rn(acc[mt][nt][half * 2]);
                dst[permh(f + 1)] = __float2half_rn(acc[mt][nt][half * 2 + 1]);
            }
        }
    }
}

// =============================================================
extern "C" void kernel_launch(void* const* d_in, const int* in_sizes, int n_in,
                              void* d_out, int out_size)
{
    const float* x   = (const float*)d_in[0];
    const float* Wk  = (const float*)d_in[1];
    const float* Wv  = (const float*)d_in[2];
    const float* Wp  = (const float*)d_in[3];
    const float* bp  = (const float*)d_in[4];
    float* Y = (float*)d_out;

    cudaFuncSetAttribute(gemm_mma, cudaFuncAttributeMaxDynamicSharedMemorySize, GEMM_SMEM);

    prep<<<4608, 256>>>(x, Wk, Wv, Wp);                    // fused prep + zero
    gemm_mma<<<dim3(8, 32), 256, GEMM_SMEM>>>(bp, Y, 0);   // K,V projection (fp16 out)
    k2_kv   <<<dim3(32, 8), 256>>>();                      // K^T V -> g_M (atomic)
    k3_av   <<<dim3(32, 16), 256>>>();                     // V @ M -> g_Ah
    gemm_mma<<<dim3(4, 32), 256, GEMM_SMEM>>>(bp, Y, 1);   // Y = A@Wp + b
}

// round 13
// speedup vs baseline: 1.8831x; 1.0786x over previous
#include <cuda_runtime.h>
#include <cuda_fp16.h>

// B=2, S=2048, D=1024, H=16, HS=64
// out = V @ (K^T @ V) / 8 per (b,h)   (no softmax, Q==V)
// R13: k3 (V@M) eliminated algebraically:
//   Y[b] = Vcat[b] @ G[b],  G[b][(h,e),n] = sum_f M[b,h,e,f] Wp[h*64+f,n]
// mode0 writes Vcat (fp16 permuted) straight into g_Ah; tiny k_g builds G;
// mode1 consumes G[b]. GEMM inner loops untouched from the R11 win.

#define S_LEN 2048
#define D_DIM 1024
#define HS    64
#define BH    32
#define MROWS 4096

// fp16 pair permutation within each 16-half group: pair order
// [p0,p4,p1,p5,p2,p6,p3,p7] -> fragment pairs (tg, tg+4) adjacent (LDS.64).
// permh(even e) is even and permh(e+1) == permh(e)+1.
__device__ __forceinline__ int permh(int k) {
    int grp = k & ~15, kk = k & 15, pr = kk >> 1, od = kk & 1;
    int s = (pr < 4) ? (2 * pr) : (2 * (pr - 4) + 1);
    return grp + 2 * s + od;
}

// ---------------- scratch (no allocs allowed) ----------------
__device__ __half g_Kh[BH * S_LEN * HS];       // [B,H,S,HS] fp16, natural
__device__ float  g_M[BH * HS * HS];           // K^T V / 8 (atomic accum)
__device__ __half g_Ah[MROWS * D_DIM];         // Vcat: [b,s,(h,e)] fp16 permuted
__device__ __half g_Xh[MROWS * D_DIM];         // x fp16 permuted
__device__ __half g_Wth[2048 * 1024];          // [Wk|Wv] K-major, permuted
__device__ __half g_Wpth[1024 * 1024];         // Wproj^T K-major, permuted
__device__ __half g_Gt[2 * 1024 * 1024];       // G[b]: rows n, k=(h,e) permuted

// =============================================================
// helpers
// =============================================================
__device__ __forceinline__ void cp16(void* dst, const void* src) {
    unsigned d;
    asm("{ .reg .u64 t; cvta.to.shared.u64 t, %1; cvt.u32.u64 %0, t; }"
        : "=r"(d) : "l"(dst));
    asm volatile("cp.async.cg.shared.global [%0], [%1], 16;" :: "r"(d), "l"(src));
}

__device__ __forceinline__ void mma16(float* d, const unsigned* a, const unsigned* b) {
    asm volatile(
        "mma.sync.aligned.m16n8k16.row.col.f32.f16.f16.f32 "
        "{%0,%1,%2,%3}, {%4,%5,%6,%7}, {%8,%9}, {%0,%1,%2,%3};"
        : "+f"(d[0]), "+f"(d[1]), "+f"(d[2]), "+f"(d[3])
        : "r"(a[0]), "r"(a[1]), "r"(a[2]), "r"(a[3]), "r"(b[0]), "r"(b[1]));
}

// =============================================================
// prep: fused xcvt + tW + tWp + g_M zeroing, dispatched by block range.
// =============================================================
__global__ __launch_bounds__(256) void prep(const float* __restrict__ x,
                                            const float* __restrict__ Wk,
                                            const float* __restrict__ Wv,
                                            const float* __restrict__ Wp)
{
    __shared__ float tile[32][33];
    const int blk = blockIdx.x, tid = threadIdx.x;

    if (blk < 1024) {                       // ---- x -> fp16 permuted ----
        int base = (blk * 256 + tid) * 16;
        float v[16];
        #pragma unroll
        for (int i = 0; i < 4; i++)
            *(float4*)(v + 4 * i) = *(const float4*)(x + base + 4 * i);
        __half2 out[8];
        #pragma unroll
        for (int p = 0; p < 8; p++) {
            int s = (p < 4) ? (2 * p) : (2 * (p - 4) + 1);
            out[s] = __floats2half2_rn(v[2 * p], v[2 * p + 1]);
        }
        *(uint4*)(g_Xh + base)     = ((uint4*)out)[0];
        *(uint4*)(g_Xh + base + 8) = ((uint4*)out)[1];
    } else if (blk < 3072) {                // ---- tW ----
        const int local = blk - 1024;
        const int bx = local & 31, by = (local >> 5) & 1, hh = local >> 6;
        const int x0 = bx * 32, y0 = by * 32;
        const int tx = tid & 31, ty = tid >> 5;
        const float* W = (hh < 16) ? Wk : Wv;
        const int h = hh & 15;
        #pragma unroll
        for (int j = 0; j < 4; j++)
            tile[ty + 8 * j][tx] = W[h * 65536 + (x0 + ty + 8 * j) * 64 + y0 + tx];
        __syncthreads();
        const int dp = x0 + permh(tx);
        #pragma unroll
        for (int j = 0; j < 4; j++)
            g_Wth[(hh * 64 + y0 + ty + 8 * j) * 1024 + dp] =
                __float2half_rn(tile[tx][ty + 8 * j]);
    } else if (blk < 4096) {                // ---- tWp ----
        const int local = blk - 3072;
        const int bx = local & 31, by = local >> 5;
        const int x0 = bx * 32, y0 = by * 32;
        const int tx = tid & 31, ty = tid >> 5;
        #pragma unroll
        for (int j = 0; j < 4; j++)
            tile[ty + 8 * j][tx] = Wp[(y0 + ty + 8 * j) * 1024 + x0 + tx];
        __syncthreads();
        const int kp = y0 + permh(tx);
        #pragma unroll
        for (int j = 0; j < 4; j++)
            g_Wpth[(x0 + ty + 8 * j) * 1024 + kp] =
                __float2half_rn(tile[tx][ty + 8 * j]);
    } else {                                // ---- zero g_M ----
        g_M[(blk - 4096) * 256 + tid] = 0.f;
    }
}

// =============================================================
// fp16 mma.sync GEMM: C[4096, N] = A[4096,1024] @ B^T (B = K-major rows)
// BM=128, BN=256, BK=64 halves, 3-stage / distance-2 prefetch, one sync/iter.
// mode 0: A=g_Xh, B=g_Wth; epilogue scatters K (natural) + Vcat (permuted).
// mode 1: A=g_Ah (Vcat), B=g_Gt[b], writes Y + bias.
// =============================================================
#define BMt 128
#define BNt 256
#define BKh 64
#define PITCHB 160
#define SA_BYTES (BMt * PITCHB)
#define SB_BYTES (BNt * PITCHB)
#define STAGE_BYTES (SA_BYTES + SB_BYTES)
#define GEMM_SMEM (3 * STAGE_BYTES)

__global__ __launch_bounds__(256, 1)
void gemm_mma(const float* __restrict__ bias,
              float* __restrict__ Y,
              int mode)
{
    extern __shared__ __align__(16) char sm[];
    const int tid = threadIdx.x, wid = tid >> 5, lane = tid & 31;
    const int g = lane >> 2, tg = lane & 3;
    const int bm = blockIdx.y * BMt, bn = blockIdx.x * BNt;

    const __half* Ag = ((mode == 0) ? g_Xh : g_Ah) + (size_t)bm * 1024;
    const __half* Bg = ((mode == 0) ? g_Wth
                                    : g_Gt + (size_t)(bm >> 11) * 1048576)
                       + (size_t)bn * 1024;

    auto prefetch = [&](int kc) {
        char* sA = sm + (kc % 3) * STAGE_BYTES;
        char* sB = sA + SA_BYTES;
        const __half* As = Ag + kc * BKh;
        const __half* Bs = Bg + kc * BKh;
        #pragma unroll
        for (int i = 0; i < 4; i++) {
            int idx = tid + i * 256;
            int m = idx >> 3, c8 = idx & 7;
            cp16(sA + m * PITCHB + c8 * 16, As + (size_t)m * 1024 + c8 * 8);
        }
        #pragma unroll
        for (int i = 0; i < 8; i++) {
            int idx = tid + i * 256;
            int n = idx >> 3, c8 = idx & 7;
            cp16(sB + n * PITCHB + c8 * 16, Bs + (size_t)n * 1024 + c8 * 8);
        }
        asm volatile("cp.async.commit_group;" ::: "memory");
    };

    prefetch(0); prefetch(1);

    const int wm = (wid & 1) * 64;
    const int wn = (wid >> 1) * 64;

    float acc[4][8][4];
    #pragma unroll
    for (int mt = 0; mt < 4; mt++)
        #pragma unroll
        for (int nt = 0; nt < 8; nt++)
            #pragma unroll
            for (int q = 0; q < 4; q++) acc[mt][nt][q] = 0.f;

    for (int kc = 0; kc < 16; kc++) {
        const char* sA = sm + (kc % 3) * STAGE_BYTES;
        const char* sB = sA + SA_BYTES;
        if (kc < 15) asm volatile("cp.async.wait_group 1;" ::: "memory");
        else         asm volatile("cp.async.wait_group 0;" ::: "memory");
        __syncthreads();
        if (kc + 2 < 16) prefetch(kc + 2);

        #pragma unroll
        for (int ks = 0; ks < 4; ks++) {
            const int koff = ks * 32 + 8 * tg;
            unsigned a[4][4], b[8][2];
            #pragma unroll
            for (int mt = 0; mt < 4; mt++) {
                const char* p = sA + (wm + mt * 16 + g) * PITCHB + koff;
                uint2 lo = *(const uint2*)p;
                uint2 hi = *(const uint2*)(p + 8 * PITCHB);
                a[mt][0] = lo.x; a[mt][1] = hi.x;
                a[mt][2] = lo.y; a[mt][3] = hi.y;
            }
            #pragma unroll
            for (int nt = 0; nt < 8; nt++) {
                uint2 bb = *(const uint2*)(sB + (wn + nt * 8 + g) * PITCHB + koff);
                b[nt][0] = bb.x; b[nt][1] = bb.y;
            }
            #pragma unroll
            for (int mt = 0; mt < 4; mt++)
                #pragma unroll
                for (int nt = 0; nt < 8; nt++)
                    mma16(acc[mt][nt], a[mt], b[nt]);
        }
    }

    // ---- epilogue ----
    const int gnw = bn + wn;                 // 64-aligned -> exactly 1 head
    if (mode == 0) {
        const int isK = (gnw < 1024);
        const int h = (gnw & 1023) >> 6;
        #pragma unroll
        for (int mt = 0; mt < 4; mt++) {
            const int m0 = bm + wm + mt * 16 + g;
            #pragma unroll
            for (int half = 0; half < 2; half++) {
                const int m = m0 + half * 8;
                const int b = m >> 11, s = m & 2047;
                if (isK) {
                    __half* dst = g_Kh + (size_t)((b * 16 + h) * 2048 + s) * 64;
                    #pragma unroll
                    for (int nt = 0; nt < 8; nt++) {
                        const int e = nt * 8 + tg * 2;
                        *(__half2*)(dst + e) =
                            __floats2half2_rn(acc[mt][nt][half * 2],
                                              acc[mt][nt][half * 2 + 1]);
                    }
                } else {
                    __half* dst = g_Ah + (size_t)(b * 2048 + s) * 1024 + h * 64;
                    #pragma unroll
                    for (int nt = 0; nt < 8; nt++) {
                        const int e = nt * 8 + tg * 2;       // logical, even
                        *(__half2*)(dst + permh(e)) =
                            __floats2half2_rn(acc[mt][nt][half * 2],
                                              acc[mt][nt][half * 2 + 1]);
                    }
                }
            }
        }
    } else {
        #pragma unroll
        for (int mt = 0; mt < 4; mt++) {
            const int m0 = bm + wm + mt * 16 + g;
            #pragma unroll
            for (int half = 0; half < 2; half++) {
                const int m = m0 + half * 8;
                float* dst = Y + (size_t)m * 1024;
                #pragma unroll
                for (int nt = 0; nt < 8; nt++) {
                    const int gn = gnw + nt * 8 + tg * 2;
                    float2 bb = *(const float2*)(bias + gn);
                    *(float2*)(dst + gn) = make_float2(acc[mt][nt][half * 2] + bb.x,
                                                       acc[mt][nt][half * 2 + 1] + bb.y);
                }
            }
        }
    }
}

// =============================================================
// Kernel 2: per-(b,h) partial M = K^T V over an S-chunk of 256 rows.
// K from g_Kh (natural); V from Vcat (g_Ah) with inverse pair-permutation
// during staging. atomicAdd into g_M with the 1/8 scale folded in.
// =============================================================
__global__ __launch_bounds__(256) void k2_kv()
{
    const int bh = blockIdx.x;
    const int b = bh >> 4, h = bh & 15;
    const int sc = blockIdx.y;
    const __half* K  = g_Kh + (size_t)(bh * S_LEN + sc * 256) * HS;
    const __half* Vc = g_Ah + (size_t)(b * S_LEN + sc * 256) * 1024 + h * 64;

    __shared__ float Ks[32][64];
    __shared__ float Vs[32][64];
    const int tid = threadIdx.x;
    const int tx = tid & 15, ty = tid >> 4;

    float acc[4][4] = {};

    for (int s0 = 0; s0 < 256; s0 += 32) {
        {
            int idx = tid * 8;
            int r = idx >> 6, c = idx & 63;
            uint4 kr = *(const uint4*)(K + (s0 + r) * HS + c);
            uint4 vr = *(const uint4*)(Vc + (size_t)(s0 + r) * 1024 + c);
            const __half2* kh = (const __half2*)&kr;
            const __half2* vh = (const __half2*)&vr;
            const int grp = c & ~15, chunk = (c >> 4) & 0 ? 0 : ((c >> 3) & 1);
            #pragma unroll
            for (int q = 0; q < 4; q++) {
                float2 kf = __half22float2(kh[q]);
                Ks[r][c + 2 * q] = kf.x; Ks[r][c + 2 * q + 1] = kf.y;
                // inverse perm: stored pair-slot ss -> logical pair p
                int ss = 4 * chunk + q;
                int p  = (ss & 1) ? (4 + (ss >> 1)) : (ss >> 1);
                int e  = grp + 2 * p;
                float2 vf = __half22float2(vh[q]);
                Vs[r][e] = vf.x; Vs[r][e + 1] = vf.y;
            }
        }
        __syncthreads();
        #pragma unroll
        for (int s = 0; s < 32; s++) {
            float4 a4 = *(const float4*)&Ks[s][ty * 4];
            float4 b4 = *(const float4*)&Vs[s][tx * 4];
            float a[4] = {a4.x, a4.y, a4.z, a4.w};
            float b[4] = {b4.x, b4.y, b4.z, b4.w};
            #pragma unroll
            for (int i = 0; i < 4; i++)
                #pragma unroll
                for (int j = 0; j < 4; j++)
                    acc[i][j] += a[i] * b[j];
        }
        __syncthreads();
    }

    float* Mb = g_M + bh * 4096;
    #pragma unroll
    for (int i = 0; i < 4; i++)
        #pragma unroll
        for (int j = 0; j < 4; j++)
            atomicAdd(&Mb[(ty * 4 + i) * 64 + tx * 4 + j], acc[i][j] * 0.125f);
}

// =============================================================
// k_g (tensor): G[b][n, h*64+permh(e)] = sum_f M[b,h,e,f] * Wp[h*64+f, n]
// A = g_Wpth rows n (already fp16 K-major permuted), B = M staged fp16
// permuted. One 256(n) x 64(e) tile per CTA, k=64. grid (4, 32).
// =============================================================
#define KGP 144                                 // 64 halves (128B) + 16B pad
__global__ __launch_bounds__(256) void k_g()
{
    __shared__ __align__(16) char sa[256 * KGP];   // A: 256 n-rows
    __shared__ __align__(16) char sb[64 * KGP];    // B: 64 e-rows

    const int bh = blockIdx.y;
    const int b = bh >> 4, h = bh & 15;
    const int bn = blockIdx.x * 256;
    const int tid = threadIdx.x, wid = tid >> 5, lane = tid & 31;
    const int g = lane >> 2, tg = lane & 3;

    // A staging: rows n_local, 64 halves from g_Wpth[(bn+n)*1024 + h*64 ..]
    const __half* Aw = g_Wpth + (size_t)bn * 1024 + h * 64;
    #pragma unroll
    for (int i = 0; i < 8; i++) {
        int idx = tid + i * 256;
        int n = idx >> 3, c8 = idx & 7;
        cp16(sa + n * KGP + c8 * 16, Aw + (size_t)n * 1024 + c8 * 8);
    }
    asm volatile("cp.async.commit_group;" ::: "memory");

    // B staging: M[b,h] fp32 -> fp16, f-permuted
    const float* Mg = g_M + bh * 4096;
    #pragma unroll
    for (int i = 0; i < 16; i++) {
        int idx = tid + i * 256;
        int e = idx >> 6, f = idx & 63;
        ((__half*)(sb + e * KGP))[permh(f)] = __float2half_rn(Mg[idx]);
    }
    asm volatile("cp.async.wait_group 0;" ::: "memory");
    __syncthreads();

    const int wm = (wid & 3) * 64;       // 4 warps along n
    const int wn = (wid >> 2) * 32;      // 2 warps along e

    float acc[4][4][4] = {};
    #pragma unroll
    for (int ks = 0; ks < 4; ks++) {
        const int koff = ks * 32 + 8 * tg;
        unsigned a[4][4], bb[4][2];
        #pragma unroll
        for (int mt = 0; mt < 4; mt++) {
            const char* p = sa + (wm + mt * 16 + g) * KGP + koff;
            uint2 lo = *(const uint2*)p;
            uint2 hi = *(const uint2*)(p + 8 * KGP);
            a[mt][0] = lo.x; a[mt][1] = hi.x;
            a[mt][2] = lo.y; a[mt][3] = hi.y;
        }
        #pragma unroll
        for (int nt = 0; nt < 4; nt++) {
            uint2 v = *(const uint2*)(sb + (wn + nt * 8 + g) * KGP + koff);
            bb[nt][0] = v.x; bb[nt][1] = v.y;
        }
        #pragma unroll
        for (int mt = 0; mt < 4; mt++)
            #pragma unroll
            for (int nt = 0; nt < 4; nt++)
                mma16(acc[mt][nt], a[mt], bb[nt]);
    }

    // epilogue: rows n, cols e -> g_Gt[b][n, h*64 + permh(e)]
    __half* Gb = g_Gt + (size_t)b * 1048576 + h * 64;
    #pragma unroll
    for (int mt = 0; mt < 4; mt++) {
        const int n0 = bn + wm + mt * 16 + g;
        #pragma unroll
        for (int half = 0; half < 2; half++) {
            __half* dst = Gb + (size_t)(n0 + half * 8) * 1024;
            #pragma unroll
            for (int nt = 0; nt < 4; nt++) {
                const int e = wn + nt * 8 + tg * 2;          // logical, even
                *(__half2*)(dst + permh(e)) =
                    __floats2half2_rn(acc[mt][nt][half * 2],
                                      acc[mt][nt][half * 2 + 1]);
            }
        }
    }
}

// =============================================================
extern "C" void kernel_launch(void* const* d_in, const int* in_sizes, int n_in,
                              void* d_out, int out_size)
{
    const float* x   = (const float*)d_in[0];
    const float* Wk  = (const float*)d_in[1];
    const float* Wv  = (const float*)d_in[2];
    const float* Wp  = (const float*)d_in[3];
    const float* bp  = (const float*)d_in[4];
    float* Y = (float*)d_out;

    cudaFuncSetAttribute(gemm_mma, cudaFuncAttributeMaxDynamicSharedMemorySize, GEMM_SMEM);

    prep<<<4608, 256>>>(x, Wk, Wv, Wp);                    // fused prep + zero
    gemm_mma<<<dim3(8, 32), 256, GEMM_SMEM>>>(bp, Y, 0);   // K (natural) + Vcat
    k2_kv<<<dim3(32, 8), 256>>>();                         // K^T V -> g_M (atomic)
    k_g  <<<dim3(4, 32), 256>>>();                         // G[b] = M @ Wp (tensor)
    gemm_mma<<<dim3(4, 32), 256, GEMM_SMEM>>>(bp, Y, 1);   // Y = Vcat@G + b
}